// round 3
// baseline (speedup 1.0000x reference)
#include <cuda_runtime.h>
#include <cstdint>
#include <cub/block/block_merge_sort.cuh>

#define BN 4
#define GN 25
#define AN 147456          // 128*128*9
#define TOTN 147456
#define NUMPOS 73728
#define CAP 131072         // pos key capacity per batch (pow2)
#define NBLK 576           // AN / 256

#define FMW 128.0f
#define MIN_POS 0.15f
#define POS_TH 0.7f
#define NEG_TH 0.3f

// ------------------ static device scratch (no allocs allowed) ------------------
__device__ unsigned int       g_negmask[BN][AN];
__device__ int                g_blockNegSum[BN][NBLK];
__device__ int                g_blockNegOff[BN][NBLK];
__device__ int                g_posCount[BN];
__device__ unsigned long long g_posKeys[BN][CAP];
__device__ unsigned int       g_negbuf[BN][TOTN];

// ------------------ tiny reset (graph-replay determinism) ---------------------
__global__ void k_zero() {
    int t = threadIdx.x;
    if (t < BN) g_posCount[t] = 0;
}

// ------------------ assignment: IoU, pos append, neg mask ---------------------
// grid (NBLK, BN), 256 threads
__global__ void k_assign(const float* __restrict__ anchors,
                         const float* __restrict__ gtb) {
    __shared__ float s_g[GN][4];
    __shared__ float s_area[GN];
    __shared__ int   s_w[8];

    int t = threadIdx.x;
    int b = blockIdx.y;
    if (t < GN) {
        float x1 = __fmul_rn(gtb[(b * GN + t) * 4 + 0], 0.125f);
        float y1 = __fmul_rn(gtb[(b * GN + t) * 4 + 1], 0.125f);
        float x2 = __fmul_rn(gtb[(b * GN + t) * 4 + 2], 0.125f);
        float y2 = __fmul_rn(gtb[(b * GN + t) * 4 + 3], 0.125f);
        s_g[t][0] = x1; s_g[t][1] = y1; s_g[t][2] = x2; s_g[t][3] = y2;
        s_area[t] = __fmul_rn(__fsub_rn(x2, x1), __fsub_rn(y2, y1));
    }
    __syncthreads();

    int a = blockIdx.x * 256 + t;

    const float4 av = *reinterpret_cast<const float4*>(
        anchors + (((long long)b * AN + a) << 2));
    float ax1 = av.x, ay1 = av.y, ax2 = av.z, ay2 = av.w;
    bool valid = (ax1 >= 0.0f) && (ay1 >= 0.0f) && (ax2 <= FMW) && (ay2 <= FMW);
    float areaA = __fmul_rn(__fsub_rn(ax2, ax1), __fsub_rn(ay2, ay1));

    float iou[GN];
    float rmax = 0.0f;
    #pragma unroll
    for (int g = 0; g < GN; g++) {
        float ltx = fmaxf(ax1, s_g[g][0]);
        float lty = fmaxf(ay1, s_g[g][1]);
        float rbx = fminf(ax2, s_g[g][2]);
        float rby = fminf(ay2, s_g[g][3]);
        float wx = fmaxf(__fsub_rn(rbx, ltx), 0.0f);
        float wy = fmaxf(__fsub_rn(rby, lty), 0.0f);
        float inter = __fmul_rn(wx, wy);
        float v = 0.0f;
        if (inter > 0.0f) {
            float uni = __fsub_rn(__fadd_rn(areaA, s_area[g]), inter);
            v = __fdiv_rn(inter, uni);
        }
        iou[g] = v;
        rmax = fmaxf(rmax, v);
    }

    unsigned nm = 0;
    #pragma unroll
    for (int g = 0; g < GN; g++) {
        float v = iou[g];
        bool pos = valid && (((v == rmax) && (v > MIN_POS)) || (v >= POS_TH));
        bool neg = valid && (v < NEG_TH) && !pos;
        if (pos) {
            int idx = atomicAdd(&g_posCount[b], 1);
            if (idx < CAP) {
                unsigned flat = (unsigned)(a * GN + g);
                unsigned long long key =
                    ((unsigned long long)__float_as_uint(v) << 32) |
                    (unsigned long long)(~flat);
                g_posKeys[b][idx] = key;
            }
        }
        if (neg) nm |= (1u << g);
    }
    g_negmask[b][a] = nm;

    // block-total neg count via warp reduce
    int cnt = __popc(nm);
    #pragma unroll
    for (int o = 16; o > 0; o >>= 1) cnt += __shfl_down_sync(~0u, cnt, o);
    if ((t & 31) == 0) s_w[t >> 5] = cnt;
    __syncthreads();
    if (t == 0) {
        int s = 0;
        #pragma unroll
        for (int w = 0; w < 8; w++) s += s_w[w];
        g_blockNegSum[b][blockIdx.x] = s;
    }
}

// ------------------ scan of per-block neg counts ------------------------------
__global__ void k_scanblocks() {
    __shared__ int s[1024];
    int b = blockIdx.x, t = threadIdx.x;
    int v = (t < NBLK) ? g_blockNegSum[b][t] : 0;
    s[t] = v;
    __syncthreads();
    for (int off = 1; off < 1024; off <<= 1) {
        int x = (t >= off) ? s[t - off] : 0;
        __syncthreads();
        s[t] += x;
        __syncthreads();
    }
    if (t < NBLK) g_blockNegOff[b][t] = s[t] - v;
}

// ------------------ scatter first TOT negs (ascending flat index) -------------
// grid (NBLK, BN), 256 threads. Smem staging -> coalesced gmem stores.
__global__ void k_negscatter() {
    __shared__ unsigned s_stage[GN * 256];  // worst case 25 negs * 256 threads
    __shared__ int s_w[8];
    int blk = blockIdx.x, b = blockIdx.y, t = threadIdx.x;
    int boff = g_blockNegOff[b][blk];
    if (boff >= TOTN) return;           // uniform early exit (most blocks)

    int a = blk * 256 + t;
    unsigned mask = g_negmask[b][a];
    int cnt = __popc(mask);

    int lane = t & 31, warp = t >> 5;
    int v = cnt;
    #pragma unroll
    for (int o = 1; o < 32; o <<= 1) {
        int u = __shfl_up_sync(~0u, v, o);
        if (lane >= o) v += u;
    }
    if (lane == 31) s_w[warp] = v;
    __syncthreads();
    if (warp == 0 && lane < 8) {
        int w = s_w[lane];
        #pragma unroll
        for (int o = 1; o < 8; o <<= 1) {
            int u = __shfl_up_sync(0xff, w, o);
            if (lane >= o) w += u;
        }
        s_w[lane] = w;
    }
    __syncthreads();
    int total = s_w[7];
    int excl = (v - cnt) + (warp ? s_w[warp - 1] : 0);

    int r = excl;
    unsigned mm = mask;
    unsigned base = (unsigned)(a * GN);
    while (mm) {
        int g = __ffs(mm) - 1;
        mm &= mm - 1;
        s_stage[r++] = base + (unsigned)g;
    }
    __syncthreads();

    int lim = min(total, TOTN - boff);
    for (int i = t; i < lim; i += 256)
        g_negbuf[b][boff + i] = s_stage[i];
}

// ------------------ positive sort: banded CUB block merge sort ----------------
// key = (iou_bits << 32) | ~flat; descending sort == iou desc, flat asc on ties.
struct KeyGreater {
    __device__ bool operator()(const unsigned long long& a,
                               const unsigned long long& b) const { return a > b; }
};

template <int ITEMS>
__global__ void __launch_bounds__(1024, 1) k_sort(int loP, int hiP) {
    constexpr int N = 1024 * ITEMS;
    int b = blockIdx.x;
    int P = g_posCount[b];
    if (P <= loP || P > hiP) return;

    typedef cub::BlockMergeSort<unsigned long long, 1024, ITEMS> Sort;
    extern __shared__ char raw[];
    typename Sort::TempStorage& temp =
        *reinterpret_cast<typename Sort::TempStorage*>(raw);

    unsigned long long items[ITEMS];
    int base = threadIdx.x * ITEMS;
    #pragma unroll
    for (int i = 0; i < ITEMS; i++) {
        int gi = base + i;
        items[i] = (gi < P) ? g_posKeys[b][gi] : 0ull;
    }
    Sort(temp).Sort(items, KeyGreater());
    #pragma unroll
    for (int i = 0; i < ITEMS; i++) {
        int gi = base + i;
        if (gi < P) g_posKeys[b][gi] = items[i];
    }
    (void)N;
}

// Fallback for P > 24576: single-block gmem bitonic per batch. Correct but slow;
// never executed for the benchmark's data distribution.
__global__ void k_sort_fallback() {
    int b = blockIdx.x;
    int P = g_posCount[b];
    if (P <= 24576) return;
    P = min(P, CAP);
    for (int i = threadIdx.x; i < CAP; i += 1024)
        if (i >= P) g_posKeys[b][i] = 0ull;
    __syncthreads();
    for (int k = 2; k <= CAP; k <<= 1) {
        for (int j = k >> 1; j > 0; j >>= 1) {
            for (int p = threadIdx.x; p < CAP / 2; p += 1024) {
                int i = (p & (j - 1)) | ((p & ~(j - 1)) << 1);
                int l = i | j;
                bool desc = ((i & k) == 0);
                unsigned long long x = g_posKeys[b][i];
                unsigned long long y = g_posKeys[b][l];
                if (desc ? (x < y) : (x > y)) {
                    g_posKeys[b][i] = y; g_posKeys[b][l] = x;
                }
            }
            __syncthreads();
        }
    }
}

// ------------------ final gather + offsets + output ---------------------------
__global__ void k_output(const float* __restrict__ anchors,
                         const float* __restrict__ gtb,
                         const int* __restrict__ cls,
                         float* __restrict__ out) {
    __shared__ float s_gx1[GN], s_gy1[GN], s_gx2[GN], s_gy2[GN];
    __shared__ float s_cls[GN];

    int t = blockIdx.x * blockDim.x + threadIdx.x;
    int b = t / TOTN;
    if (b >= BN) return;
    int j = t % TOTN;

    if (threadIdx.x < GN) {
        const float* gp = gtb + (b * GN + threadIdx.x) * 4;
        s_gx1[threadIdx.x] = gp[0] * 0.125f;
        s_gy1[threadIdx.x] = gp[1] * 0.125f;
        s_gx2[threadIdx.x] = gp[2] * 0.125f;
        s_gy2[threadIdx.x] = gp[3] * 0.125f;
        s_cls[threadIdx.x] = (float)cls[b * GN + threadIdx.x];
    }
    __syncthreads();

    int P = g_posCount[b];
    int m = min(P, NUMPOS);

    unsigned flat;
    float obj;
    if (j < m) {
        unsigned long long key = g_posKeys[b][j];
        flat = ~((unsigned)key);
        obj = 1.0f;
    } else {
        flat = g_negbuf[b][j - m];
        obj = 0.0f;
    }

    int ai = (int)(flat / GN);
    int gi = (int)(flat % GN);

    const float4 av = *reinterpret_cast<const float4*>(
        anchors + (((long long)b * AN + ai) << 2));
    float ax1 = av.x, ay1 = av.y, ax2 = av.z, ay2 = av.w;

    float gx1 = s_gx1[gi], gy1 = s_gy1[gi];
    float gx2 = s_gx2[gi], gy2 = s_gy2[gi];

    float acx = (ax1 + ax2) * 0.5f, acy = (ay1 + ay2) * 0.5f;
    float aw = ax2 - ax1, ah = ay2 - ay1;
    float gcx = (gx1 + gx2) * 0.5f, gcy = (gy1 + gy2) * 0.5f;
    float gw = gx2 - gx1, gh = gy2 - gy1;

    float tx = (gcx - acx) / aw;
    float ty = (gcy - acy) / ah;
    float tw = logf(gw / aw);
    float th = logf(gh / ah);

    long long r = (long long)b * TOTN + j;
    const long long O_OBJ = (long long)BN * TOTN * 4;
    const long long O_CLS = O_OBJ + (long long)BN * TOTN;
    const long long O_OFF = O_CLS + (long long)BN * TOTN;

    out[r * 4 + 0] = ax1;
    out[r * 4 + 1] = ay1;
    out[r * 4 + 2] = ax2;
    out[r * 4 + 3] = ay2;
    out[O_OBJ + r] = obj;
    out[O_CLS + r] = s_cls[gi];
    out[O_OFF + r * 4 + 0] = tx;
    out[O_OFF + r * 4 + 1] = ty;
    out[O_OFF + r * 4 + 2] = tw;
    out[O_OFF + r * 4 + 3] = th;
}

// ------------------------------------------------------------------------------
extern "C" void kernel_launch(void* const* d_in, const int* in_sizes, int n_in,
                              void* d_out, int out_size) {
    const float* anchors = (const float*)d_in[0];
    const float* gtb     = (const float*)d_in[1];
    const int*   cls     = (const int*)d_in[2];
    float*       out     = (float*)d_out;

    size_t s4  = sizeof(typename cub::BlockMergeSort<unsigned long long, 1024, 4>::TempStorage);
    size_t s12 = sizeof(typename cub::BlockMergeSort<unsigned long long, 1024, 12>::TempStorage);
    size_t s24 = sizeof(typename cub::BlockMergeSort<unsigned long long, 1024, 24>::TempStorage);
    cudaFuncSetAttribute(k_sort<4>,  cudaFuncAttributeMaxDynamicSharedMemorySize, (int)s4);
    cudaFuncSetAttribute(k_sort<12>, cudaFuncAttributeMaxDynamicSharedMemorySize, (int)s12);
    cudaFuncSetAttribute(k_sort<24>, cudaFuncAttributeMaxDynamicSharedMemorySize, (int)s24);

    k_zero<<<1, 32>>>();
    k_assign<<<dim3(NBLK, BN), 256>>>(anchors, gtb);
    k_scanblocks<<<BN, 1024>>>();
    k_negscatter<<<dim3(NBLK, BN), 256>>>();

    k_sort<4><<<BN, 1024, s4>>>(0, 4096);
    k_sort<12><<<BN, 1024, s12>>>(4096, 12288);
    k_sort<24><<<BN, 1024, s24>>>(12288, 24576);
    k_sort_fallback<<<BN, 1024>>>();

    k_output<<<(BN * TOTN + 255) / 256, 256>>>(anchors, gtb, cls, out);
}

// round 4
// speedup vs baseline: 17.5579x; 17.5579x over previous
#include <cuda_runtime.h>
#include <cstdint>
#include <cub/device/device_radix_sort.cuh>

#define BN 4
#define GN 25
#define AN 147456          // 128*128*9
#define TOTN 147456
#define NUMPOS 73728
#define CAP 131072         // pos key capacity per batch (pow2)
#define NBLK 576           // AN / 256
#define NKEY (BN * CAP)    // 524288

#define FMW 128.0f
#define MIN_POS 0.15f
#define POS_TH 0.7f
#define NEG_TH 0.3f

// ------------------ static device scratch (no allocs allowed) ------------------
__device__ unsigned int       g_negmask[BN][AN];
__device__ int                g_blockNegSum[BN][NBLK];
__device__ int                g_blockNegOff[BN][NBLK];
__device__ int                g_posCount[BN];
__device__ unsigned long long g_posKeys[NKEY];     // input keys (padded)
__device__ unsigned long long g_keysOut[NKEY];     // sorted keys
__device__ unsigned char      g_sortTemp[24 << 20];// cub temp storage
__device__ unsigned int       g_negbuf[BN][TOTN];

// ------------------ reset counters + pad-fill keys -----------------------------
__global__ void k_zero() {
    int t = blockIdx.x * blockDim.x + threadIdx.x;
    if (t < BN) g_posCount[t] = 0;
    // pad every slot with (b << 52); real keys overwrite [0, P_b)
    for (int i = t; i < NKEY; i += gridDim.x * blockDim.x) {
        unsigned long long b = (unsigned long long)(i / CAP);
        g_posKeys[i] = b << 52;
    }
}

// ------------------ assignment: IoU, pos append, neg mask ---------------------
// grid (NBLK, BN), 256 threads
__global__ void k_assign(const float* __restrict__ anchors,
                         const float* __restrict__ gtb) {
    __shared__ float s_g[GN][4];
    __shared__ float s_area[GN];
    __shared__ int   s_w[8];

    int t = threadIdx.x;
    int b = blockIdx.y;
    if (t < GN) {
        float x1 = __fmul_rn(gtb[(b * GN + t) * 4 + 0], 0.125f);
        float y1 = __fmul_rn(gtb[(b * GN + t) * 4 + 1], 0.125f);
        float x2 = __fmul_rn(gtb[(b * GN + t) * 4 + 2], 0.125f);
        float y2 = __fmul_rn(gtb[(b * GN + t) * 4 + 3], 0.125f);
        s_g[t][0] = x1; s_g[t][1] = y1; s_g[t][2] = x2; s_g[t][3] = y2;
        s_area[t] = __fmul_rn(__fsub_rn(x2, x1), __fsub_rn(y2, y1));
    }
    __syncthreads();

    int a = blockIdx.x * 256 + t;

    const float4 av = *reinterpret_cast<const float4*>(
        anchors + (((long long)b * AN + a) << 2));
    float ax1 = av.x, ay1 = av.y, ax2 = av.z, ay2 = av.w;
    bool valid = (ax1 >= 0.0f) && (ay1 >= 0.0f) && (ax2 <= FMW) && (ay2 <= FMW);
    float areaA = __fmul_rn(__fsub_rn(ax2, ax1), __fsub_rn(ay2, ay1));

    float iou[GN];
    float rmax = 0.0f;
    #pragma unroll
    for (int g = 0; g < GN; g++) {
        float ltx = fmaxf(ax1, s_g[g][0]);
        float lty = fmaxf(ay1, s_g[g][1]);
        float rbx = fminf(ax2, s_g[g][2]);
        float rby = fminf(ay2, s_g[g][3]);
        float wx = fmaxf(__fsub_rn(rbx, ltx), 0.0f);
        float wy = fmaxf(__fsub_rn(rby, lty), 0.0f);
        float inter = __fmul_rn(wx, wy);
        float v = 0.0f;
        if (inter > 0.0f) {
            float uni = __fsub_rn(__fadd_rn(areaA, s_area[g]), inter);
            v = __fdiv_rn(inter, uni);
        }
        iou[g] = v;
        rmax = fmaxf(rmax, v);
    }

    unsigned nm = 0;
    #pragma unroll
    for (int g = 0; g < GN; g++) {
        float v = iou[g];
        bool pos = valid && (((v == rmax) && (v > MIN_POS)) || (v >= POS_TH));
        bool neg = valid && (v < NEG_TH) && !pos;
        if (pos) {
            int idx = atomicAdd(&g_posCount[b], 1);
            if (idx < CAP) {
                unsigned flat = (unsigned)(a * GN + g);
                unsigned long long key =
                    ((unsigned long long)b << 52) |
                    ((unsigned long long)__float_as_uint(v) << 22) |
                    (unsigned long long)(0x3FFFFFu ^ flat);
                g_posKeys[b * CAP + idx] = key;
            }
        }
        if (neg) nm |= (1u << g);
    }
    g_negmask[b][a] = nm;

    int cnt = __popc(nm);
    #pragma unroll
    for (int o = 16; o > 0; o >>= 1) cnt += __shfl_down_sync(~0u, cnt, o);
    if ((t & 31) == 0) s_w[t >> 5] = cnt;
    __syncthreads();
    if (t == 0) {
        int s = 0;
        #pragma unroll
        for (int w = 0; w < 8; w++) s += s_w[w];
        g_blockNegSum[b][blockIdx.x] = s;
    }
}

// ------------------ scan of per-block neg counts ------------------------------
__global__ void k_scanblocks() {
    __shared__ int s[1024];
    int b = blockIdx.x, t = threadIdx.x;
    int v = (t < NBLK) ? g_blockNegSum[b][t] : 0;
    s[t] = v;
    __syncthreads();
    for (int off = 1; off < 1024; off <<= 1) {
        int x = (t >= off) ? s[t - off] : 0;
        __syncthreads();
        s[t] += x;
        __syncthreads();
    }
    if (t < NBLK) g_blockNegOff[b][t] = s[t] - v;
}

// ------------------ scatter first TOT negs (ascending flat index) -------------
// grid (NBLK, BN), 256 threads. Smem staging -> coalesced gmem stores.
__global__ void k_negscatter() {
    __shared__ unsigned s_stage[GN * 256];
    __shared__ int s_w[8];
    int blk = blockIdx.x, b = blockIdx.y, t = threadIdx.x;
    int boff = g_blockNegOff[b][blk];
    if (boff >= TOTN) return;

    int a = blk * 256 + t;
    unsigned mask = g_negmask[b][a];
    int cnt = __popc(mask);

    int lane = t & 31, warp = t >> 5;
    int v = cnt;
    #pragma unroll
    for (int o = 1; o < 32; o <<= 1) {
        int u = __shfl_up_sync(~0u, v, o);
        if (lane >= o) v += u;
    }
    if (lane == 31) s_w[warp] = v;
    __syncthreads();
    if (warp == 0 && lane < 8) {
        int w = s_w[lane];
        #pragma unroll
        for (int o = 1; o < 8; o <<= 1) {
            int u = __shfl_up_sync(0xff, w, o);
            if (lane >= o) w += u;
        }
        s_w[lane] = w;
    }
    __syncthreads();
    int total = s_w[7];
    int excl = (v - cnt) + (warp ? s_w[warp - 1] : 0);

    int r = excl;
    unsigned mm = mask;
    unsigned base = (unsigned)(a * GN);
    while (mm) {
        int g = __ffs(mm) - 1;
        mm &= mm - 1;
        s_stage[r++] = base + (unsigned)g;
    }
    __syncthreads();

    int lim = min(total, TOTN - boff);
    for (int i = t; i < lim; i += 256)
        g_negbuf[b][boff + i] = s_stage[i];
}

// ------------------ final gather + offsets + output ---------------------------
__global__ void k_output(const float* __restrict__ anchors,
                         const float* __restrict__ gtb,
                         const int* __restrict__ cls,
                         float* __restrict__ out) {
    __shared__ float s_gx1[GN], s_gy1[GN], s_gx2[GN], s_gy2[GN];
    __shared__ float s_cls[GN];

    int t = blockIdx.x * blockDim.x + threadIdx.x;
    int b = t / TOTN;
    if (b >= BN) return;
    int j = t % TOTN;

    if (threadIdx.x < GN) {
        const float* gp = gtb + (b * GN + threadIdx.x) * 4;
        s_gx1[threadIdx.x] = gp[0] * 0.125f;
        s_gy1[threadIdx.x] = gp[1] * 0.125f;
        s_gx2[threadIdx.x] = gp[2] * 0.125f;
        s_gy2[threadIdx.x] = gp[3] * 0.125f;
        s_cls[threadIdx.x] = (float)cls[b * GN + threadIdx.x];
    }
    __syncthreads();

    int P = g_posCount[b];
    int m = min(P, NUMPOS);

    unsigned flat;
    float obj;
    if (j < m) {
        // descending sort: batch b occupies block (BN-1-b)*CAP
        unsigned long long key = g_keysOut[(BN - 1 - b) * CAP + j];
        flat = 0x3FFFFFu ^ ((unsigned)key & 0x3FFFFFu);
        obj = 1.0f;
    } else {
        flat = g_negbuf[b][j - m];
        obj = 0.0f;
    }

    int ai = (int)(flat / GN);
    int gi = (int)(flat % GN);

    const float4 av = *reinterpret_cast<const float4*>(
        anchors + (((long long)b * AN + ai) << 2));
    float ax1 = av.x, ay1 = av.y, ax2 = av.z, ay2 = av.w;

    float gx1 = s_gx1[gi], gy1 = s_gy1[gi];
    float gx2 = s_gx2[gi], gy2 = s_gy2[gi];

    float acx = (ax1 + ax2) * 0.5f, acy = (ay1 + ay2) * 0.5f;
    float aw = ax2 - ax1, ah = ay2 - ay1;
    float gcx = (gx1 + gx2) * 0.5f, gcy = (gy1 + gy2) * 0.5f;
    float gw = gx2 - gx1, gh = gy2 - gy1;

    float tx = (gcx - acx) / aw;
    float ty = (gcy - acy) / ah;
    float tw = logf(gw / aw);
    float th = logf(gh / ah);

    long long r = (long long)b * TOTN + j;
    const long long O_OBJ = (long long)BN * TOTN * 4;
    const long long O_CLS = O_OBJ + (long long)BN * TOTN;
    const long long O_OFF = O_CLS + (long long)BN * TOTN;

    out[r * 4 + 0] = ax1;
    out[r * 4 + 1] = ay1;
    out[r * 4 + 2] = ax2;
    out[r * 4 + 3] = ay2;
    out[O_OBJ + r] = obj;
    out[O_CLS + r] = s_cls[gi];
    out[O_OFF + r * 4 + 0] = tx;
    out[O_OFF + r * 4 + 1] = ty;
    out[O_OFF + r * 4 + 2] = tw;
    out[O_OFF + r * 4 + 3] = th;
}

// ------------------------------------------------------------------------------
extern "C" void kernel_launch(void* const* d_in, const int* in_sizes, int n_in,
                              void* d_out, int out_size) {
    const float* anchors = (const float*)d_in[0];
    const float* gtb     = (const float*)d_in[1];
    const int*   cls     = (const int*)d_in[2];
    float*       out     = (float*)d_out;

    void* d_keys_in  = nullptr;
    void* d_keys_out = nullptr;
    void* d_temp     = nullptr;
    cudaGetSymbolAddress(&d_keys_in,  g_posKeys);
    cudaGetSymbolAddress(&d_keys_out, g_keysOut);
    cudaGetSymbolAddress(&d_temp,     g_sortTemp);

    size_t temp_bytes = 0;
    cub::DeviceRadixSort::SortKeysDescending(
        nullptr, temp_bytes,
        (const unsigned long long*)d_keys_in, (unsigned long long*)d_keys_out,
        NKEY, 0, 54);
    if (temp_bytes > (24u << 20)) temp_bytes = (24u << 20);  // overprovisioned

    k_zero<<<512, 256>>>();
    k_assign<<<dim3(NBLK, BN), 256>>>(anchors, gtb);
    k_scanblocks<<<BN, 1024>>>();
    k_negscatter<<<dim3(NBLK, BN), 256>>>();

    cub::DeviceRadixSort::SortKeysDescending(
        d_temp, temp_bytes,
        (const unsigned long long*)d_keys_in, (unsigned long long*)d_keys_out,
        NKEY, 0, 54);

    k_output<<<(BN * TOTN + 255) / 256, 256>>>(anchors, gtb, cls, out);
}

// round 5
// speedup vs baseline: 23.2319x; 1.3232x over previous
#include <cuda_runtime.h>
#include <cstdint>
#include <cub/device/device_radix_sort.cuh>

#define BN 4
#define GN 25
#define AN 147456          // 128*128*9
#define TOTN 147456
#define NUMPOS 73728
#define CAP 131072         // pos capacity per batch (pow2)
#define NBLK 576           // AN / 256
#define NKEY (BN * CAP)    // 524288

#define FMW 128.0f
#define MIN_POS 0.15f
#define POS_TH 0.7f
#define NEG_TH 0.3f

// ------------------ static device scratch (no allocs allowed) ------------------
__device__ unsigned int  g_posmask[BN][AN];
__device__ unsigned int  g_negmask[BN][AN];
__device__ long long     g_blockSum[BN][NBLK];   // (pos<<32)|neg per block
__device__ long long     g_blockOff[BN][NBLK];   // exclusive offsets
__device__ int           g_posCount[BN];
__device__ unsigned int  g_keysIn[NKEY];
__device__ unsigned int  g_valsIn[NKEY];
__device__ unsigned int  g_keysOut[NKEY];
__device__ unsigned int  g_valsOut[NKEY];
__device__ unsigned char g_sortTemp[24 << 20];
__device__ unsigned int  g_negbuf[BN][TOTN];

// ------------------ pad-fill keys (graph-replay determinism) -------------------
__global__ void k_zero() {
    int t = blockIdx.x * blockDim.x + threadIdx.x;
    for (int i = t; i < NKEY; i += gridDim.x * blockDim.x)
        g_keysIn[i] = ((unsigned)(i / CAP)) << 30;   // iou=0 pad, sinks within batch
}

// ------------------ IoU helper (must be bit-identical in both kernels) --------
__device__ __forceinline__ float iou_one(float ax1, float ay1, float ax2, float ay2,
                                         float areaA,
                                         const float* sg, float sarea) {
    float ltx = fmaxf(ax1, sg[0]);
    float lty = fmaxf(ay1, sg[1]);
    float rbx = fminf(ax2, sg[2]);
    float rby = fminf(ay2, sg[3]);
    float wx = fmaxf(__fsub_rn(rbx, ltx), 0.0f);
    float wy = fmaxf(__fsub_rn(rby, lty), 0.0f);
    float inter = __fmul_rn(wx, wy);
    float v = 0.0f;
    if (inter > 0.0f) {
        float uni = __fsub_rn(__fadd_rn(areaA, sarea), inter);
        v = __fdiv_rn(inter, uni);
    }
    return v;
}

// ------------------ assignment: masks + packed block sums ---------------------
// grid (NBLK, BN), 256 threads
__global__ void k_assign(const float* __restrict__ anchors,
                         const float* __restrict__ gtb) {
    __shared__ float s_g[GN][4];
    __shared__ float s_area[GN];
    __shared__ long long s_w[8];

    int t = threadIdx.x;
    int b = blockIdx.y;
    if (t < GN) {
        float x1 = __fmul_rn(gtb[(b * GN + t) * 4 + 0], 0.125f);
        float y1 = __fmul_rn(gtb[(b * GN + t) * 4 + 1], 0.125f);
        float x2 = __fmul_rn(gtb[(b * GN + t) * 4 + 2], 0.125f);
        float y2 = __fmul_rn(gtb[(b * GN + t) * 4 + 3], 0.125f);
        s_g[t][0] = x1; s_g[t][1] = y1; s_g[t][2] = x2; s_g[t][3] = y2;
        s_area[t] = __fmul_rn(__fsub_rn(x2, x1), __fsub_rn(y2, y1));
    }
    __syncthreads();

    int a = blockIdx.x * 256 + t;

    const float4 av = *reinterpret_cast<const float4*>(
        anchors + (((long long)b * AN + a) << 2));
    float ax1 = av.x, ay1 = av.y, ax2 = av.z, ay2 = av.w;
    bool valid = (ax1 >= 0.0f) && (ay1 >= 0.0f) && (ax2 <= FMW) && (ay2 <= FMW);
    float areaA = __fmul_rn(__fsub_rn(ax2, ax1), __fsub_rn(ay2, ay1));

    float iou[GN];
    float rmax = 0.0f;
    #pragma unroll
    for (int g = 0; g < GN; g++) {
        float v = iou_one(ax1, ay1, ax2, ay2, areaA, s_g[g], s_area[g]);
        iou[g] = v;
        rmax = fmaxf(rmax, v);
    }

    unsigned pm = 0, nm = 0;
    #pragma unroll
    for (int g = 0; g < GN; g++) {
        float v = iou[g];
        bool pos = valid && (((v == rmax) && (v > MIN_POS)) || (v >= POS_TH));
        bool neg = valid && (v < NEG_TH) && !pos;
        if (pos) pm |= (1u << g);
        if (neg) nm |= (1u << g);
    }
    g_posmask[b][a] = pm;
    g_negmask[b][a] = nm;

    long long cnt = ((long long)__popc(pm) << 32) | (unsigned)__popc(nm);
    #pragma unroll
    for (int o = 16; o > 0; o >>= 1) cnt += __shfl_down_sync(~0u, cnt, o);
    if ((t & 31) == 0) s_w[t >> 5] = cnt;
    __syncthreads();
    if (t == 0) {
        long long s = 0;
        #pragma unroll
        for (int w = 0; w < 8; w++) s += s_w[w];
        g_blockSum[b][blockIdx.x] = s;
    }
}

// ------------------ scan of packed per-block counts ---------------------------
__global__ void k_scanblocks() {
    __shared__ long long s[1024];
    int b = blockIdx.x, t = threadIdx.x;
    long long v = (t < NBLK) ? g_blockSum[b][t] : 0;
    s[t] = v;
    __syncthreads();
    for (int off = 1; off < 1024; off <<= 1) {
        long long x = (t >= off) ? s[t - off] : 0;
        __syncthreads();
        s[t] += x;
        __syncthreads();
    }
    if (t < NBLK) g_blockOff[b][t] = s[t] - v;
    if (t == NBLK - 1) g_posCount[b] = (int)(s[t] >> 32);
}

// ------------------ fused pos+neg scatter (deterministic flat order) ----------
// grid (NBLK, BN), 256 threads
__global__ void k_scatter(const float* __restrict__ anchors,
                          const float* __restrict__ gtb) {
    __shared__ float s_g[GN][4];
    __shared__ float s_area[GN];
    __shared__ unsigned s_stage[GN * 256];
    __shared__ int s_w[8];

    int blk = blockIdx.x, b = blockIdx.y, t = threadIdx.x;
    long long off = g_blockOff[b][blk];
    int posOff = (int)(off >> 32);
    int negOff = (int)(off & 0xFFFFFFFFll);
    bool doNeg = (negOff < TOTN);

    if (t < GN) {
        float x1 = __fmul_rn(gtb[(b * GN + t) * 4 + 0], 0.125f);
        float y1 = __fmul_rn(gtb[(b * GN + t) * 4 + 1], 0.125f);
        float x2 = __fmul_rn(gtb[(b * GN + t) * 4 + 2], 0.125f);
        float y2 = __fmul_rn(gtb[(b * GN + t) * 4 + 3], 0.125f);
        s_g[t][0] = x1; s_g[t][1] = y1; s_g[t][2] = x2; s_g[t][3] = y2;
        s_area[t] = __fmul_rn(__fsub_rn(x2, x1), __fsub_rn(y2, y1));
    }
    __syncthreads();

    int a = blk * 256 + t;
    unsigned pm = g_posmask[b][a];
    unsigned nm = doNeg ? g_negmask[b][a] : 0u;

    // packed block scan: (posCnt<<16)|negCnt  (block totals <= 6400 < 2^16)
    int packed = (__popc(pm) << 16) | __popc(nm);
    int lane = t & 31, warp = t >> 5;
    int v = packed;
    #pragma unroll
    for (int o = 1; o < 32; o <<= 1) {
        int u = __shfl_up_sync(~0u, v, o);
        if (lane >= o) v += u;
    }
    if (lane == 31) s_w[warp] = v;
    __syncthreads();
    if (warp == 0 && lane < 8) {
        int w = s_w[lane];
        #pragma unroll
        for (int o = 1; o < 8; o <<= 1) {
            int u = __shfl_up_sync(0xff, w, o);
            if (lane >= o) w += u;
        }
        s_w[lane] = w;
    }
    __syncthreads();
    int total = s_w[7];
    int excl = (v - packed) + (warp ? s_w[warp - 1] : 0);
    int posExcl = excl >> 16;
    int negExcl = excl & 0xFFFF;
    int negTotal = total & 0xFFFF;

    // --- positives: recompute IoU for set bits, write key/val at exact rank ---
    if (pm) {
        const float4 av = *reinterpret_cast<const float4*>(
            anchors + (((long long)b * AN + a) << 2));
        float ax1 = av.x, ay1 = av.y, ax2 = av.z, ay2 = av.w;
        float areaA = __fmul_rn(__fsub_rn(ax2, ax1), __fsub_rn(ay2, ay1));
        int r = posOff + posExcl;
        unsigned mm = pm;
        while (mm) {
            int g = __ffs(mm) - 1;
            mm &= mm - 1;
            if (r < CAP) {
                float vio = iou_one(ax1, ay1, ax2, ay2, areaA, s_g[g], s_area[g]);
                g_keysIn[b * CAP + r] = ((unsigned)b << 30) | __float_as_uint(vio);
                g_valsIn[b * CAP + r] = (unsigned)(a * GN + g);
            }
            r++;
        }
    }

    // --- negatives: smem stage then coalesced copy ---
    if (doNeg) {
        int r = negExcl;
        unsigned mm = nm;
        unsigned base = (unsigned)(a * GN);
        while (mm) {
            int g = __ffs(mm) - 1;
            mm &= mm - 1;
            s_stage[r++] = base + (unsigned)g;
        }
        __syncthreads();
        int lim = min(negTotal, TOTN - negOff);
        for (int i = t; i < lim; i += 256)
            g_negbuf[b][negOff + i] = s_stage[i];
    }
}

// ------------------ final gather + offsets + output ---------------------------
__global__ void k_output(const float* __restrict__ anchors,
                         const float* __restrict__ gtb,
                         const int* __restrict__ cls,
                         float* __restrict__ out) {
    __shared__ float s_gx1[GN], s_gy1[GN], s_gx2[GN], s_gy2[GN];
    __shared__ float s_cls[GN];

    int t = blockIdx.x * blockDim.x + threadIdx.x;
    int b = t / TOTN;
    if (b >= BN) return;
    int j = t % TOTN;

    if (threadIdx.x < GN) {
        const float* gp = gtb + (b * GN + threadIdx.x) * 4;
        s_gx1[threadIdx.x] = gp[0] * 0.125f;
        s_gy1[threadIdx.x] = gp[1] * 0.125f;
        s_gx2[threadIdx.x] = gp[2] * 0.125f;
        s_gy2[threadIdx.x] = gp[3] * 0.125f;
        s_cls[threadIdx.x] = (float)cls[b * GN + threadIdx.x];
    }
    __syncthreads();

    int P = g_posCount[b];
    int m = min(P, NUMPOS);

    unsigned flat;
    float obj;
    if (j < m) {
        // descending sort => batch b occupies block (BN-1-b)*CAP
        flat = g_valsOut[(BN - 1 - b) * CAP + j];
        obj = 1.0f;
    } else {
        flat = g_negbuf[b][j - m];
        obj = 0.0f;
    }

    int ai = (int)(flat / GN);
    int gi = (int)(flat % GN);

    const float4 av = *reinterpret_cast<const float4*>(
        anchors + (((long long)b * AN + ai) << 2));
    float ax1 = av.x, ay1 = av.y, ax2 = av.z, ay2 = av.w;

    float gx1 = s_gx1[gi], gy1 = s_gy1[gi];
    float gx2 = s_gx2[gi], gy2 = s_gy2[gi];

    float acx = (ax1 + ax2) * 0.5f, acy = (ay1 + ay2) * 0.5f;
    float aw = ax2 - ax1, ah = ay2 - ay1;
    float gcx = (gx1 + gx2) * 0.5f, gcy = (gy1 + gy2) * 0.5f;
    float gw = gx2 - gx1, gh = gy2 - gy1;

    float tx = (gcx - acx) / aw;
    float ty = (gcy - acy) / ah;
    float tw = logf(gw / aw);
    float th = logf(gh / ah);

    long long r = (long long)b * TOTN + j;
    const long long O_OBJ = (long long)BN * TOTN * 4;
    const long long O_CLS = O_OBJ + (long long)BN * TOTN;
    const long long O_OFF = O_CLS + (long long)BN * TOTN;

    out[r * 4 + 0] = ax1;
    out[r * 4 + 1] = ay1;
    out[r * 4 + 2] = ax2;
    out[r * 4 + 3] = ay2;
    out[O_OBJ + r] = obj;
    out[O_CLS + r] = s_cls[gi];
    out[O_OFF + r * 4 + 0] = tx;
    out[O_OFF + r * 4 + 1] = ty;
    out[O_OFF + r * 4 + 2] = tw;
    out[O_OFF + r * 4 + 3] = th;
}

// ------------------------------------------------------------------------------
extern "C" void kernel_launch(void* const* d_in, const int* in_sizes, int n_in,
                              void* d_out, int out_size) {
    const float* anchors = (const float*)d_in[0];
    const float* gtb     = (const float*)d_in[1];
    const int*   cls     = (const int*)d_in[2];
    float*       out     = (float*)d_out;

    void *d_ki, *d_ko, *d_vi, *d_vo, *d_temp;
    cudaGetSymbolAddress(&d_ki, g_keysIn);
    cudaGetSymbolAddress(&d_ko, g_keysOut);
    cudaGetSymbolAddress(&d_vi, g_valsIn);
    cudaGetSymbolAddress(&d_vo, g_valsOut);
    cudaGetSymbolAddress(&d_temp, g_sortTemp);

    size_t temp_bytes = 0;
    cub::DeviceRadixSort::SortPairsDescending(
        nullptr, temp_bytes,
        (const unsigned*)d_ki, (unsigned*)d_ko,
        (const unsigned*)d_vi, (unsigned*)d_vo,
        NKEY, 0, 32);
    if (temp_bytes > (24u << 20)) temp_bytes = (24u << 20);

    k_zero<<<512, 256>>>();
    k_assign<<<dim3(NBLK, BN), 256>>>(anchors, gtb);
    k_scanblocks<<<BN, 1024>>>();
    k_scatter<<<dim3(NBLK, BN), 256>>>(anchors, gtb);

    cub::DeviceRadixSort::SortPairsDescending(
        d_temp, temp_bytes,
        (const unsigned*)d_ki, (unsigned*)d_ko,
        (const unsigned*)d_vi, (unsigned*)d_vo,
        NKEY, 0, 32);

    k_output<<<(BN * TOTN + 255) / 256, 256>>>(anchors, gtb, cls, out);
}